// round 3
// baseline (speedup 1.0000x reference)
#include <cuda_runtime.h>

#define DI   128
#define DS   16
#define DM   64
#define LSEQ 4096
#define BSZ  16
#define RTOT (BSZ*LSEQ)
#define NC   64
#define CT   64

// ---------------- static scratch (no allocation) ----------------
__device__ float g_u   [(size_t)RTOT*DI];
__device__ float g_gate[(size_t)RTOT*DI];
__device__ float g_uc  [(size_t)RTOT*DI];
__device__ float g_dt  [(size_t)RTOT*DI];
__device__ float g_bc  [(size_t)RTOT*32];
__device__ float g_P[BSZ*DI*NC*DS];
__device__ float g_Q[BSZ*DI*NC*DS];
__device__ float g_W[BSZ*DI*NC*DS];
__device__ float g_S[BSZ*DI*NC];
__device__ float g_Y[BSZ*DI];

__device__ __forceinline__ float siluf(float v){
    return __fdividef(v, 1.f + __expf(-v));
}

// =====================================================================
// K1: xz = x @ in_proj_w^T ; cols 0..127 -> g_u, cols 128..255 -> silu -> g_gate
// 256 thr, tile 64 rows x 256 cols, f32x2 packed FMA.
// =====================================================================
__global__ void __launch_bounds__(256,2) k_inproj(const float* __restrict__ x,
                                                  const float* __restrict__ w)
{
    __shared__ __align__(16) float ws[32*268];
    __shared__ __align__(16) float xs[64*32];
    const int tid = threadIdx.x;
    const int r0  = blockIdx.x * 64;
    const int ty  = tid >> 5, tx = tid & 31;

    unsigned long long acc[8][4];
#pragma unroll
    for (int i=0;i<8;i++){
#pragma unroll
        for (int j=0;j<4;j++) acc[i][j] = 0ULL;
    }

    for (int kk=0; kk<64; kk+=32){
        __syncthreads();
        for (int i=tid; i<256*32; i+=256){
            int e = i >> 5, kq = i & 31;
            ws[kq*268 + e] = w[e*64 + kk + kq];
        }
        for (int i=tid; i<64*8; i+=256){
            int rr = i >> 3, q = i & 7;
            float4 v = *(const float4*)(x + (size_t)(r0+rr)*64 + kk + q*4);
            *(float4*)(xs + rr*32 + q*4) = v;
        }
        __syncthreads();

        const float* xrow = xs + ty*8*32;
#pragma unroll 4
        for (int k=0;k<32;k++){
            unsigned long long bb[4];
            const float* wr = ws + k*268 + tx*2;
#pragma unroll
            for (int j=0;j<4;j++) bb[j] = *(const unsigned long long*)(wr + j*64);
#pragma unroll
            for (int i=0;i<8;i++){
                unsigned int au = __float_as_uint(xrow[i*32 + k]);
                unsigned long long aa;
                asm("mov.b64 %0,{%1,%1};" : "=l"(aa) : "r"(au));
#pragma unroll
                for (int j=0;j<4;j++)
                    asm("fma.rn.f32x2 %0,%1,%2,%0;"
                        : "+l"(acc[i][j]) : "l"(aa), "l"(bb[j]));
            }
        }
    }
#pragma unroll
    for (int i=0;i<8;i++){
        size_t r = (size_t)(r0 + ty*8 + i);
#pragma unroll
        for (int j=0;j<4;j++){
            unsigned int lo, hi;
            asm("mov.b64 {%0,%1},%2;" : "=r"(lo), "=r"(hi) : "l"(acc[i][j]));
            float a = __uint_as_float(lo), bv = __uint_as_float(hi);
            int e = j*64 + tx*2;
            if (e < 128){
                g_u[r*DI + e]   = a;
                g_u[r*DI + e+1] = bv;
            } else {
                g_gate[r*DI + e-128] = siluf(a);
                g_gate[r*DI + e-127] = siluf(bv);
            }
        }
    }
}

// =====================================================================
// K2: causal depthwise conv+SiLU -> uc ; x_dbl = uc@x_proj^T -> (dt_r,B,C);
//     dt = softplus(dt_r@dt_proj^T + b). Tile = 32 timesteps of one batch.
// =====================================================================
__global__ void __launch_bounds__(256,2) k_mid(const float* __restrict__ cw,
                                               const float* __restrict__ cb,
                                               const float* __restrict__ xw,
                                               const float* __restrict__ dtw,
                                               const float* __restrict__ dtb)
{
    __shared__ __align__(16) float ucs[32*132];
    __shared__ __align__(16) float xws[36*132];
    __shared__ float xds[32*40];
    __shared__ float cws[DI*4];
    __shared__ float cbs[DI];
    __shared__ float dtws[4*132];
    __shared__ float dtbs[DI];

    const int tid = threadIdx.x;
    const int b   = blockIdx.x >> 7;
    const int l0  = (blockIdx.x & 127) * 32;

    for (int i=tid;i<36*128;i+=256){ int f=i>>7, k=i&127; xws[f*132+k] = xw[i]; }
    for (int i=tid;i<512;i+=256) cws[i] = cw[i];
    for (int i=tid;i<512;i+=256){ int e=i>>2, r=i&3; dtws[r*132+e] = dtw[i]; }
    if (tid < 128){ cbs[tid] = cb[tid]; dtbs[tid] = dtb[tid]; }
    __syncthreads();

    // conv + SiLU
    for (int i=tid;i<32*128;i+=256){
        int l = i >> 7, e = i & 127;
        int lg = l0 + l;
        float s = cbs[e];
#pragma unroll
        for (int j=0;j<4;j++){
            int lj = lg - 3 + j;
            if (lj >= 0) s += g_u[((size_t)(b*LSEQ + lj))*DI + e] * cws[e*4+j];
        }
        float v = siluf(s);
        ucs[l*132+e] = v;
        g_uc[((size_t)(b*LSEQ + lg))*DI + e] = v;
    }
    __syncthreads();

    // x_dbl = uc @ x_proj^T  (36 outs, groups of 4)
    for (int idx=tid; idx<32*9; idx+=256){
        int l = idx / 9, f0 = (idx % 9)*4;
        float a0=0.f,a1=0.f,a2=0.f,a3=0.f;
        const float* up = ucs + l*132;
        const float* w0 = xws + (f0+0)*132;
        const float* w1 = xws + (f0+1)*132;
        const float* w2 = xws + (f0+2)*132;
        const float* w3 = xws + (f0+3)*132;
#pragma unroll 8
        for (int k=0;k<128;k+=4){
            float4 u4 = *(const float4*)(up + k);
            float4 q0 = *(const float4*)(w0 + k);
            float4 q1 = *(const float4*)(w1 + k);
            float4 q2 = *(const float4*)(w2 + k);
            float4 q3 = *(const float4*)(w3 + k);
            a0 += u4.x*q0.x + u4.y*q0.y + u4.z*q0.z + u4.w*q0.w;
            a1 += u4.x*q1.x + u4.y*q1.y + u4.z*q1.z + u4.w*q1.w;
            a2 += u4.x*q2.x + u4.y*q2.y + u4.z*q2.z + u4.w*q2.w;
            a3 += u4.x*q3.x + u4.y*q3.y + u4.z*q3.z + u4.w*q3.w;
        }
        xds[l*40+f0+0]=a0; xds[l*40+f0+1]=a1;
        xds[l*40+f0+2]=a2; xds[l*40+f0+3]=a3;
    }
    __syncthreads();

    // B/C out
    for (int i=tid;i<32*32;i+=256){
        int l = i >> 5, q = i & 31;
        g_bc[((size_t)(b*LSEQ + l0 + l))*32 + q] = xds[l*40 + 4 + q];
    }
    // dt = softplus(dt_r @ dt_proj^T + b)
    for (int i=tid;i<32*128;i+=256){
        int l = i >> 7, dd = i & 127;
        const float* xr = xds + l*40;
        float v = dtbs[dd];
#pragma unroll
        for (int r=0;r<4;r++) v += xr[r]*dtws[r*132+dd];
        float sp = fmaxf(v,0.f) + log1pf(__expf(-fabsf(v)));
        g_dt[((size_t)(b*LSEQ + l0 + l))*DI + dd] = sp;
    }
}

// =====================================================================
// K3: chunk scan. Block=(c,b), thread=d. Emits per (b,d,c):
//   P[s]=prod a, Q[s]=h_local, W[s]=sum gate*C*cumprod, S=sum gate*(<h_loc,C>+D*uc)
// =====================================================================
__global__ void __launch_bounds__(128) k_scan(const float* __restrict__ A_log,
                                              const float* __restrict__ Dp)
{
    __shared__ float Bs[CT*DS], Cs[CT*DS];
    const int d = threadIdx.x;
    const int c = blockIdx.x, b = blockIdx.y;
    const int l0 = c*CT;

    for (int i=d; i<CT*32; i+=128){
        int t = i >> 5, q = i & 31;
        float v = g_bc[((size_t)(b*LSEQ + l0 + t))*32 + q];
        if (q < 16) Bs[t*DS+q] = v; else Cs[t*DS+q-16] = v;
    }
    float A[DS];
#pragma unroll
    for (int s=0;s<DS;s++) A[s] = -expf(A_log[d*DS+s]);
    const float Dd = Dp[d];
    float R[DS], hl[DS], W[DS];
#pragma unroll
    for (int s=0;s<DS;s++){ R[s]=1.f; hl[s]=0.f; W[s]=0.f; }
    float Sacc = 0.f;
    __syncthreads();

    const float* dtp = g_dt   + ((size_t)(b*LSEQ + l0))*DI + d;
    const float* ucp = g_uc   + ((size_t)(b*LSEQ + l0))*DI + d;
    const float* gp  = g_gate + ((size_t)(b*LSEQ + l0))*DI + d;

    for (int t=0; t<CT; t++){
        float dt = dtp[(size_t)t*DI];
        float uc = ucp[(size_t)t*DI];
        float gate = gp[(size_t)t*DI];
        float g = dt*uc;
        float yl = 0.f;
#pragma unroll
        for (int s=0;s<DS;s++){
            float a = __expf(dt*A[s]);
            R[s] *= a;
            hl[s] = a*hl[s] + g*Bs[t*DS+s];
            float Ct = Cs[t*DS+s];
            W[s] += gate*(Ct*R[s]);
            yl += hl[s]*Ct;
        }
        Sacc += gate*(yl + Dd*uc);
    }
    size_t base = (((size_t)(b*DI + d))*NC + c)*DS;
#pragma unroll
    for (int s=0;s<DS;s++){
        g_P[base+s] = R[s];
        g_Q[base+s] = hl[s];
        g_W[base+s] = W[s];
    }
    g_S[(size_t)(b*DI + d)*NC + c] = Sacc;
}

// =====================================================================
// K4: serial combine over chunks; warp per (b,d), lane=s (lanes>=16 idle-zero)
// =====================================================================
__global__ void __launch_bounds__(256) k_combine()
{
    int warp = threadIdx.x >> 5, lane = threadIdx.x & 31;
    int pair = blockIdx.x*8 + warp;           // = b*DI + d
    size_t base = (size_t)pair*NC*DS;
    float h = 0.f, acc = 0.f, sacc = 0.f;
    for (int c=0;c<NC;c++){
        float p=0.f,q=0.f,w=0.f;
        if (lane < DS){
            p = g_P[base + c*DS + lane];
            q = g_Q[base + c*DS + lane];
            w = g_W[base + c*DS + lane];
        }
        acc += w*h;
        h = p*h + q;
        if (lane == 0) sacc += g_S[(size_t)pair*NC + c];
    }
#pragma unroll
    for (int o=16;o>0;o>>=1) acc += __shfl_down_sync(0xFFFFFFFFu, acc, o);
    if (lane == 0) g_Y[pair] = acc + sacc;
}

// =====================================================================
// K5: logits[b,n] = (1/L) sum_d Y[b,d]*eff[n,d] + cls_b[n],
//     eff[n,d] = sum_m cls_w[n,m]*out_proj_w[m,d]
// =====================================================================
__global__ void k_final(const float* __restrict__ outw,
                        const float* __restrict__ clsw,
                        const float* __restrict__ clsb,
                        float* __restrict__ out)
{
    __shared__ float eff[2*DI];
    int tid = threadIdx.x;
    {
        int n = tid >> 7, dd = tid & 127;
        float e = 0.f;
        for (int m=0;m<DM;m++) e += clsw[n*DM+m]*outw[m*DI+dd];
        eff[n*DI+dd] = e;
    }
    __syncthreads();
    if (tid < 32){
        int b = tid >> 1, n = tid & 1;
        float a = 0.f;
        for (int dd=0;dd<DI;dd++) a += g_Y[b*DI+dd]*eff[n*DI+dd];
        out[b*2+n] = a*(1.f/LSEQ) + clsb[n];
    }
}

extern "C" void kernel_launch(void* const* d_in, const int* in_sizes, int n_in,
                              void* d_out, int out_size)
{
    const float* x    = (const float*)d_in[0];
    const float* inw  = (const float*)d_in[1];
    const float* cw   = (const float*)d_in[2];
    const float* cb   = (const float*)d_in[3];
    const float* xw   = (const float*)d_in[4];
    const float* dtw  = (const float*)d_in[5];
    const float* dtb  = (const float*)d_in[6];
    const float* alog = (const float*)d_in[7];
    const float* Dp   = (const float*)d_in[8];
    const float* ow   = (const float*)d_in[9];
    const float* cls  = (const float*)d_in[10];
    const float* clsb = (const float*)d_in[11];
    (void)in_sizes; (void)n_in; (void)out_size;

    k_inproj<<<RTOT/64, 256>>>(x, inw);
    k_mid<<<BSZ*(LSEQ/32), 256>>>(cw, cb, xw, dtw, dtb);
    dim3 g3(NC, BSZ);
    k_scan<<<g3, 128>>>(alog, Dp);
    k_combine<<<BSZ*DI/8, 256>>>();
    k_final<<<1, 256>>>(ow, cls, clsb, (float*)d_out);
}